// round 4
// baseline (speedup 1.0000x reference)
#include <cuda_runtime.h>
#include <cuda_fp16.h>
#include <cstdint>
#include <cstddef>

#define TOKENS 32768
#define HIDDEN 2048
#define INTER  1408
#define NEXP   16
#define TPE    2048

#define BM 128
#define BK 32
#define PAD_A 40      // A smem row halfs
#define BNS 264       // B smem row halfs (256 data + 8 pad)
#define ASTAGES 4
#define SMEM_BYTES ((ASTAGES * BM * PAD_A + 2 * BK * BNS) * 2)

// ---------------- static device scratch ----------------
__device__ __align__(128) __half g_Xh[(size_t)TOKENS * HIDDEN];   // X fp16
__device__ __align__(128) __half g_H [(size_t)TOKENS * INTER];    // h = swiglu(gate,up)

// ---------------- helpers ----------------
__device__ __forceinline__ uint32_t smem_u32(const void* p) {
    return (uint32_t)__cvta_generic_to_shared(p);
}
__device__ __forceinline__ void cp_async16(uint32_t dst, const void* src) {
    asm volatile("cp.async.cg.shared.global [%0], [%1], 16;\n" :: "r"(dst), "l"(src));
}
__device__ __forceinline__ void cp_commit() {
    asm volatile("cp.async.commit_group;\n" ::: "memory");
}
template <int N>
__device__ __forceinline__ void cp_wait() {
    asm volatile("cp.async.wait_group %0;\n" :: "n"(N) : "memory");
}
__device__ __forceinline__ void ldsm_x4(uint32_t addr, uint32_t& r0, uint32_t& r1,
                                        uint32_t& r2, uint32_t& r3) {
    asm volatile("ldmatrix.sync.aligned.m8n8.x4.shared.b16 {%0,%1,%2,%3}, [%4];\n"
                 : "=r"(r0), "=r"(r1), "=r"(r2), "=r"(r3) : "r"(addr));
}
__device__ __forceinline__ void ldsm_x4_trans(uint32_t addr, uint32_t& r0, uint32_t& r1,
                                              uint32_t& r2, uint32_t& r3) {
    asm volatile("ldmatrix.sync.aligned.m8n8.x4.trans.shared.b16 {%0,%1,%2,%3}, [%4];\n"
                 : "=r"(r0), "=r"(r1), "=r"(r2), "=r"(r3) : "r"(addr));
}
__device__ __forceinline__ void mma16816(float* c, const uint32_t* a, const uint32_t* b) {
    asm volatile(
        "mma.sync.aligned.m16n8k16.row.col.f32.f16.f16.f32 "
        "{%0,%1,%2,%3}, {%4,%5,%6,%7}, {%8,%9}, {%0,%1,%2,%3};\n"
        : "+f"(c[0]), "+f"(c[1]), "+f"(c[2]), "+f"(c[3])
        : "r"(a[0]), "r"(a[1]), "r"(a[2]), "r"(a[3]), "r"(b[0]), "r"(b[1]));
}

// ---------------- 1. X fp32 -> fp16 ----------------
__global__ void convert_x_kernel(const float* __restrict__ x, size_t n8) {
    size_t i = (size_t)blockIdx.x * blockDim.x + threadIdx.x;
    if (i >= n8) return;
    const float4* x4 = (const float4*)x;
    float4 a = x4[2 * i];
    float4 b = x4[2 * i + 1];
    union { __half2 h[4]; uint4 u; } r;
    r.h[0] = __floats2half2_rn(a.x, a.y);
    r.h[1] = __floats2half2_rn(a.z, a.w);
    r.h[2] = __floats2half2_rn(b.x, b.y);
    r.h[3] = __floats2half2_rn(b.z, b.w);
    ((uint4*)g_Xh)[i] = r.u;
}

// ============================================================================
// GEMM core shared structure: BM=128 x 256-smem-col B tile, 16 warps (4m x 4n),
// warp tile 32m x 64cols. A: m-major fp16 via 4-stage cp.async + ldmatrix.
// B: k-major fp16 smem filled from fp32 global (convert in regs), 2-stage,
// fragments via ldmatrix.trans.
// ============================================================================

// ---------------- 2. fused gate+up GEMM + SwiGLU -> g_H ----------------
// B tile cols c: p=c>>5 (16-col output block pair), h=(c>>4)&1 (0=gate,1=up),
// w=c&15. output n = nB + p*16 + w, nB = blockIdx.y*128.
__global__ __launch_bounds__(512) void gemm1_kernel(
    const float* __restrict__ Wg, const float* __restrict__ Wu) {
    extern __shared__ __half sm[];
    __half (*sA)[BM][PAD_A] = (__half(*)[BM][PAD_A])sm;
    __half (*sB)[BK][BNS]   = (__half(*)[BK][BNS])(sm + ASTAGES * BM * PAD_A);

    const int tid = threadIdx.x;
    const int mBase = blockIdx.x * BM;
    const int nB = blockIdx.y * 128;
    const int e = blockIdx.x >> 4;            // mBase / TPE
    const int NK = HIDDEN / BK;               // 64

    // A loader: thread -> (row tid>>2, 8-half chunk (tid&3)*8)
    const int ar = tid >> 2, ac = (tid & 3) * 8;
    const __half* gA = g_Xh + (size_t)(mBase + ar) * HIDDEN + ac;
    uint32_t sAaddr[ASTAGES];
    #pragma unroll
    for (int s = 0; s < ASTAGES; s++) sAaddr[s] = smem_u32(&sA[s][ar][ac]);

    // B loader: thread -> (k-row tid>>4, 16-col block q=tid&15)
    const int br = tid >> 4;                  // 0..31
    const int bq = tid & 15;
    const int bh = bq & 1;                    // 0=gate 1=up
    const int bp = bq >> 1;                   // 0..7
    const float* gB = (bh ? Wu : Wg)
        + ((size_t)e * HIDDEN + br) * INTER + nB + bp * 16;
    __half* sBst[2];
    sBst[0] = &sB[0][br][bq * 16];
    sBst[1] = &sB[1][br][bq * 16];

    float bReg[16];
    float acc[2 * 8 * 4];
    #pragma unroll
    for (int i = 0; i < 64; i++) acc[i] = 0.f;

    const int w = tid >> 5, lane = tid & 31;
    const int wm = (w >> 2) * 32;             // 0,32,64,96
    const int wn = (w & 3) * 64;              // 0,64,128,192
    const int lrow = lane & 15;
    const int lkb = (lane >> 4) * 8;
    // B ldsm address components
    const int bsr = (lane & 7) + 8 * ((lane >> 3) & 1);   // k within 16
    const int bsc = 8 * (lane >> 4);                      // +0/+8 col

    // prologue: A stages 0,1 + B regs stage 0
    cp_async16(sAaddr[0], gA);
    cp_commit();
    cp_async16(sAaddr[1], gA + BK);
    cp_commit();
    {
        const float4* p = (const float4*)gB;
        #pragma unroll
        for (int i = 0; i < 4; i++) {
            float4 v = p[i];
            bReg[4 * i] = v.x; bReg[4 * i + 1] = v.y;
            bReg[4 * i + 2] = v.z; bReg[4 * i + 3] = v.w;
        }
    }

    #pragma unroll 1
    for (int k = 0; k < NK; ++k) {
        const int st2 = k & 1, st4 = k & 3;
        // store B stage k from regs
        {
            union { __half2 h2[8]; uint4 q[2]; } u;
            #pragma unroll
            for (int i = 0; i < 8; i++)
                u.h2[i] = __floats2half2_rn(bReg[2 * i], bReg[2 * i + 1]);
            uint4* d = (uint4*)sBst[st2];
            d[0] = u.q[0];
            d[1] = u.q[1];
        }
        // load B regs for stage k+1
        if (k + 1 < NK) {
            const float4* p = (const float4*)(gB + (size_t)(k + 1) * BK * INTER);
            #pragma unroll
            for (int i = 0; i < 4; i++) {
                float4 v = p[i];
                bReg[4 * i] = v.x; bReg[4 * i + 1] = v.y;
                bReg[4 * i + 2] = v.z; bReg[4 * i + 3] = v.w;
            }
        }
        // A stage k+2
        if (k + 2 < NK) cp_async16(sAaddr[(k + 2) & 3], gA + (k + 2) * BK);
        cp_commit();
        cp_wait<1>();
        __syncthreads();

        #pragma unroll
        for (int kk = 0; kk < BK; kk += 16) {
            uint32_t a[2][4];
            uint32_t b[8][2];
            #pragma unroll
            for (int mt = 0; mt < 2; mt++)
                ldsm_x4(smem_u32(&sA[st4][wm + mt * 16 + lrow][kk + lkb]),
                        a[mt][0], a[mt][1], a[mt][2], a[mt][3]);
            #pragma unroll
            for (int i = 0; i < 4; i++) {
                uint32_t r0, r1, r2, r3;
                ldsm_x4_trans(smem_u32(&sB[st2][kk + bsr][wn + i * 16 + bsc]),
                              r0, r1, r2, r3);
                b[2 * i][0] = r0;     b[2 * i][1] = r1;
                b[2 * i + 1][0] = r2; b[2 * i + 1][1] = r3;
            }
            #pragma unroll
            for (int mt = 0; mt < 2; mt++)
                #pragma unroll
                for (int nt = 0; nt < 8; nt++)
                    mma16816(&acc[(mt * 8 + nt) * 4], a[mt], b[nt]);
        }
    }

    // epilogue: SwiGLU on (gate nt, up nt+2) pairs, write h fp16
    const int gr = lane >> 2, gc = (lane & 3) * 2;
    #pragma unroll
    for (int mt = 0; mt < 2; mt++) {
        #pragma unroll
        for (int nt = 0; nt < 8; nt++) {
            if ((nt >> 1) & 1) continue;        // nt in {0,1,4,5} are gate
            const float* g = &acc[(mt * 8 + nt) * 4];
            const float* u = &acc[(mt * 8 + nt + 2) * 4];
            int p = 2 * (w & 3) + (nt >> 2);
            int n = nB + p * 16 + (nt & 1) * 8 + gc;
            int token = mBase + wm + mt * 16 + gr;
            float h0 = g[0] * u[0] / (1.f + __expf(-g[0]));
            float h1 = g[1] * u[1] / (1.f + __expf(-g[1]));
            float h2 = g[2] * u[2] / (1.f + __expf(-g[2]));
            float h3 = g[3] * u[3] / (1.f + __expf(-g[3]));
            *(__half2*)&g_H[(size_t)token * INTER + n] = __floats2half2_rn(h0, h1);
            *(__half2*)&g_H[(size_t)(token + 8) * INTER + n] = __floats2half2_rn(h2, h3);
        }
    }
}

// ---------------- 3. down GEMM: out[T,H] = h @ Wd_e, fp32 out ----------------
__global__ __launch_bounds__(512) void gemm2_kernel(
    const float* __restrict__ Wd, float* __restrict__ out) {
    extern __shared__ __half sm[];
    __half (*sA)[BM][PAD_A] = (__half(*)[BM][PAD_A])sm;
    __half (*sB)[BK][BNS]   = (__half(*)[BK][BNS])(sm + ASTAGES * BM * PAD_A);

    const int tid = threadIdx.x;
    const int mBase = blockIdx.x * BM;
    const int nB = blockIdx.y * 256;
    const int e = blockIdx.x >> 4;
    const int NK = INTER / BK;                // 44

    const int ar = tid >> 2, ac = (tid & 3) * 8;
    const __half* gA = g_H + (size_t)(mBase + ar) * INTER + ac;
    uint32_t sAaddr[ASTAGES];
    #pragma unroll
    for (int s = 0; s < ASTAGES; s++) sAaddr[s] = smem_u32(&sA[s][ar][ac]);

    const int br = tid >> 4;
    const int bq = tid & 15;
    const float* gB = Wd + ((size_t)e * INTER + br) * HIDDEN + nB + bq * 16;
    __half* sBst[2];
    sBst[0] = &sB[0][br][bq * 16];
    sBst[1] = &sB[1][br][bq * 16];

    float bReg[16];
    float acc[2 * 8 * 4];
    #pragma unroll
    for (int i = 0; i < 64; i++) acc[i] = 0.f;

    const int w = tid >> 5, lane = tid & 31;
    const int wm = (w >> 2) * 32;
    const int wn = (w & 3) * 64;
    const int lrow = lane & 15;
    const int lkb = (lane >> 4) * 8;
    const int bsr = (lane & 7) + 8 * ((lane >> 3) & 1);
    const int bsc = 8 * (lane >> 4);

    cp_async16(sAaddr[0], gA);
    cp_commit();
    cp_async16(sAaddr[1], gA + BK);
    cp_commit();
    {
        const float4* p = (const float4*)gB;
        #pragma unroll
        for (int i = 0; i < 4; i++) {
            float4 v = p[i];
            bReg[4 * i] = v.x; bReg[4 * i + 1] = v.y;
            bReg[4 * i + 2] = v.z; bReg[4 * i + 3] = v.w;
        }
    }

    #pragma unroll 1
    for (int k = 0; k < NK; ++k) {
        const int st2 = k & 1, st4 = k & 3;
        {
            union { __half2 h2[8]; uint4 q[2]; } u;
            #pragma unroll
            for (int i = 0; i < 8; i++)
                u.h2[i] = __floats2half2_rn(bReg[2 * i], bReg[2 * i + 1]);
            uint4* d = (uint4*)sBst[st2];
            d[0] = u.q[0];
            d[1] = u.q[1];
        }
        if (k + 1 < NK) {
            const float4* p = (const float4*)(gB + (size_t)(k + 1) * BK * HIDDEN);
            #pragma unroll
            for (int i = 0; i < 4; i++) {
                float4 v = p[i];
                bReg[4 * i] = v.x; bReg[4 * i + 1] = v.y;
                bReg[4 * i + 2] = v.z; bReg[4 * i + 3] = v.w;
            }
        }
        if (k + 2 < NK) cp_async16(sAaddr[(k + 2) & 3], gA + (k + 2) * BK);
        cp_commit();
        cp_wait<1>();
        __syncthreads();

        #pragma unroll
        for (int kk = 0; kk < BK; kk += 16) {
            uint32_t a[2][4];
            uint32_t b[8][2];
            #pragma unroll
            for (int mt = 0; mt < 2; mt++)
                ldsm_x4(smem_u32(&sA[st4][wm + mt * 16 + lrow][kk + lkb]),
                        a[mt][0], a[mt][1], a[mt][2], a[mt][3]);
            #pragma unroll
            for (int i = 0; i < 4; i++) {
                uint32_t r0, r1, r2, r3;
                ldsm_x4_trans(smem_u32(&sB[st2][kk + bsr][wn + i * 16 + bsc]),
                              r0, r1, r2, r3);
                b[2 * i][0] = r0;     b[2 * i][1] = r1;
                b[2 * i + 1][0] = r2; b[2 * i + 1][1] = r3;
            }
            #pragma unroll
            for (int mt = 0; mt < 2; mt++)
                #pragma unroll
                for (int nt = 0; nt < 8; nt++)
                    mma16816(&acc[(mt * 8 + nt) * 4], a[mt], b[nt]);
        }
    }

    const int gr = lane >> 2, gc = (lane & 3) * 2;
    #pragma unroll
    for (int mt = 0; mt < 2; mt++) {
        #pragma unroll
        for (int nt = 0; nt < 8; nt++) {
            const float* c = &acc[(mt * 8 + nt) * 4];
            int n = nB + wn + nt * 8 + gc;
            int token = mBase + wm + mt * 16 + gr;
            *(float2*)&out[(size_t)token * HIDDEN + n] = make_float2(c[0], c[1]);
            *(float2*)&out[(size_t)(token + 8) * HIDDEN + n] = make_float2(c[2], c[3]);
        }
    }
}

// ---------------- launch ----------------
extern "C" void kernel_launch(void* const* d_in, const int* in_sizes, int n_in,
                              void* d_out, int out_size) {
    const float* x  = (const float*)d_in[0];
    const float* wg = (const float*)d_in[1];
    const float* wu = (const float*)d_in[2];
    const float* wd = (const float*)d_in[3];
    (void)in_sizes; (void)n_in; (void)out_size;

    cudaFuncSetAttribute(gemm1_kernel, cudaFuncAttributeMaxDynamicSharedMemorySize,
                         SMEM_BYTES);
    cudaFuncSetAttribute(gemm2_kernel, cudaFuncAttributeMaxDynamicSharedMemorySize,
                         SMEM_BYTES);

    // 1. X -> fp16
    size_t n8 = (size_t)TOKENS * HIDDEN / 8;
    convert_x_kernel<<<(unsigned)((n8 + 255) / 256), 256>>>(x, n8);

    // 2. fused gate+up GEMM + SwiGLU -> g_H
    gemm1_kernel<<<dim3(TOKENS / BM, INTER / 128), 512, SMEM_BYTES>>>(wg, wu);

    // 3. down GEMM -> d_out fp32
    gemm2_kernel<<<dim3(TOKENS / BM, HIDDEN / 256), 512, SMEM_BYTES>>>(
        wd, (float*)d_out);
}

// round 5
// speedup vs baseline: 1.2020x; 1.2020x over previous
#include <cuda_runtime.h>
#include <cuda_fp16.h>
#include <cstdint>
#include <cstddef>

#define TOKENS 32768
#define HIDDEN 2048
#define INTER  1408
#define NEXP   16
#define TPE    2048

#define BM 128
#define BK 32
#define PAD 40
#define NSTAGE 4
#define BROWS 256   // B smem n-rows per stage (gate128+up128, or 256 out cols)
#define SMEM_BYTES ((NSTAGE * BM * PAD + NSTAGE * BROWS * PAD) * 2)

// ---------------- static device scratch ----------------
__device__ __align__(128) __half g_Xh[(size_t)TOKENS * HIDDEN];
__device__ __align__(128) __half g_Wg[(size_t)NEXP * INTER * HIDDEN];   // [e][n][k]
__device__ __align__(128) __half g_Wu[(size_t)NEXP * INTER * HIDDEN];   // [e][n][k]
__device__ __align__(128) __half g_Wd[(size_t)NEXP * HIDDEN * INTER];   // [e][n][k]
__device__ __align__(128) __half g_H [(size_t)TOKENS * INTER];          // swiglu out

// ---------------- helpers ----------------
__device__ __forceinline__ uint32_t smem_u32(const void* p) {
    return (uint32_t)__cvta_generic_to_shared(p);
}
__device__ __forceinline__ void cp_async16(uint32_t dst, const void* src) {
    asm volatile("cp.async.cg.shared.global [%0], [%1], 16;\n" :: "r"(dst), "l"(src));
}
__device__ __forceinline__ void cp_commit() {
    asm volatile("cp.async.commit_group;\n" ::: "memory");
}
template <int N>
__device__ __forceinline__ void cp_wait() {
    asm volatile("cp.async.wait_group %0;\n" :: "n"(N) : "memory");
}
__device__ __forceinline__ void ldsm_x4(uint32_t addr, uint32_t& r0, uint32_t& r1,
                                        uint32_t& r2, uint32_t& r3) {
    asm volatile("ldmatrix.sync.aligned.m8n8.x4.shared.b16 {%0,%1,%2,%3}, [%4];\n"
                 : "=r"(r0), "=r"(r1), "=r"(r2), "=r"(r3) : "r"(addr));
}
__device__ __forceinline__ void mma16816(float* c, const uint32_t* a, const uint32_t* b) {
    asm volatile(
        "mma.sync.aligned.m16n8k16.row.col.f32.f16.f16.f32 "
        "{%0,%1,%2,%3}, {%4,%5,%6,%7}, {%8,%9}, {%0,%1,%2,%3};\n"
        : "+f"(c[0]), "+f"(c[1]), "+f"(c[2]), "+f"(c[3])
        : "r"(a[0]), "r"(a[1]), "r"(a[2]), "r"(a[3]), "r"(b[0]), "r"(b[1]));
}

// ---------------- 1. X fp32 -> fp16 ----------------
__global__ void convert_x_kernel(const float* __restrict__ x, size_t n8) {
    size_t i = (size_t)blockIdx.x * blockDim.x + threadIdx.x;
    if (i >= n8) return;
    const float4* x4 = (const float4*)x;
    float4 a = x4[2 * i];
    float4 b = x4[2 * i + 1];
    union { __half2 h[4]; uint4 u; } r;
    r.h[0] = __floats2half2_rn(a.x, a.y);
    r.h[1] = __floats2half2_rn(a.z, a.w);
    r.h[2] = __floats2half2_rn(b.x, b.y);
    r.h[3] = __floats2half2_rn(b.z, b.w);
    ((uint4*)g_Xh)[i] = r.u;
}

// ---------------- 2. weight transpose+convert: [e][K][N] f32 -> [e][N][K] f16 ----------------
__global__ __launch_bounds__(256) void wconv_kernel(const float* __restrict__ src,
                                                    int dstSel, int K, int N) {
    __shared__ __half s[64][72];
    __half* dst = (dstSel == 0) ? g_Wg : (dstSel == 1) ? g_Wu : g_Wd;
    int e = blockIdx.z;
    int n0 = blockIdx.x * 64, k0 = blockIdx.y * 64;
    const float* sp = src + (size_t)e * K * N + (size_t)k0 * N + n0;
    int tid = threadIdx.x;
    int nc = (tid & 15) * 4;
    #pragma unroll
    for (int p = 0; p < 4; p++) {
        int kr = (tid >> 4) + p * 16;
        float4 v = *(const float4*)(sp + (size_t)kr * N + nc);
        s[nc + 0][kr] = __float2half_rn(v.x);
        s[nc + 1][kr] = __float2half_rn(v.y);
        s[nc + 2][kr] = __float2half_rn(v.z);
        s[nc + 3][kr] = __float2half_rn(v.w);
    }
    __syncthreads();
    __half* dp = dst + (size_t)e * N * K + (size_t)n0 * K + k0;
    int nr = tid >> 2;
    #pragma unroll
    for (int it = 0; it < 2; it++) {
        int c = (tid & 3) + it * 4;
        *(uint4*)(dp + (size_t)nr * K + c * 8) = *(uint4*)&s[nr][c * 8];
    }
}

// ============================================================================
// GEMM core: BM=128, B tile 256 n-rows, BK=32, 4-stage cp.async.
// 16 warps (4m x 4n), warp tile 32m x 64n-rows-of-B.
// B is n-major [n][k] fp16 (pre-transposed weights), non-trans ldmatrix.
// ============================================================================

// ---------------- 3. fused gate+up GEMM + SwiGLU -> g_H (fp16) ----------------
__global__ __launch_bounds__(512, 1) void gemm1_kernel() {
    extern __shared__ __half sm[];
    __half (*sA)[BM][PAD]   = (__half(*)[BM][PAD])sm;
    __half (*sB)[BROWS][PAD] = (__half(*)[BROWS][PAD])(sm + NSTAGE * BM * PAD);

    const int tid = threadIdx.x;
    const int mBase = blockIdx.x * BM;
    const int nB = blockIdx.y * 128;
    const int e = blockIdx.x >> 4;
    const int NK = HIDDEN / BK;               // 64

    // loaders: row = tid>>2, 8-half chunk = (tid&3)*8
    const int lr = tid >> 2, lc = (tid & 3) * 8;
    const __half* gA  = g_Xh + (size_t)(mBase + lr) * HIDDEN + lc;
    const __half* gBg = g_Wg + ((size_t)e * INTER + nB + lr) * HIDDEN + lc;
    const __half* gBu = g_Wu + ((size_t)e * INTER + nB + lr) * HIDDEN + lc;

    uint32_t aAd[NSTAGE], bAd0[NSTAGE], bAd1[NSTAGE];
    #pragma unroll
    for (int s = 0; s < NSTAGE; s++) {
        aAd[s]  = smem_u32(&sA[s][lr][lc]);
        bAd0[s] = smem_u32(&sB[s][lr][lc]);
        bAd1[s] = smem_u32(&sB[s][lr + 128][lc]);
    }
    auto load_stage = [&](int s, int k0) {
        cp_async16(aAd[s],  gA  + k0);
        cp_async16(bAd0[s], gBg + k0);
        cp_async16(bAd1[s], gBu + k0);
    };

    float acc[2 * 8 * 4];
    #pragma unroll
    for (int i = 0; i < 64; i++) acc[i] = 0.f;

    const int w = tid >> 5, lane = tid & 31;
    const int wm = (w >> 2) * 32;             // 0,32,64,96
    const int wn = (w & 3) * 32;              // 0,32,64,96 (within 128 gate cols)
    const int lrow = lane & 15;
    const int lkb = (lane >> 4) * 8;

    #pragma unroll
    for (int i = 0; i < NSTAGE - 1; i++) { load_stage(i, i * BK); cp_commit(); }

    #pragma unroll 1
    for (int k = 0; k < NK; ++k) {
        cp_wait<NSTAGE - 2>();
        __syncthreads();
        int kn = k + NSTAGE - 1;
        if (kn < NK) load_stage(kn & 3, kn * BK);
        cp_commit();
        const int st = k & 3;
        #pragma unroll
        for (int kk = 0; kk < BK; kk += 16) {
            uint32_t a[2][4];
            uint32_t b[8][2];
            #pragma unroll
            for (int mt = 0; mt < 2; mt++)
                ldsm_x4(smem_u32(&sA[st][wm + mt * 16 + lrow][kk + lkb]),
                        a[mt][0], a[mt][1], a[mt][2], a[mt][3]);
            // gate rows wn..wn+31, up rows 128+wn..
            #pragma unroll
            for (int bt = 0; bt < 2; bt++) {
                uint32_t r0, r1, r2, r3;
                ldsm_x4(smem_u32(&sB[st][wn + bt * 16 + lrow][kk + lkb]), r0, r1, r2, r3);
                b[bt * 2][0] = r0;     b[bt * 2][1] = r2;
                b[bt * 2 + 1][0] = r1; b[bt * 2 + 1][1] = r3;
            }
            #pragma unroll
            for (int bt = 0; bt < 2; bt++) {
                uint32_t r0, r1, r2, r3;
                ldsm_x4(smem_u32(&sB[st][128 + wn + bt * 16 + lrow][kk + lkb]), r0, r1, r2, r3);
                b[4 + bt * 2][0] = r0;     b[4 + bt * 2][1] = r2;
                b[4 + bt * 2 + 1][0] = r1; b[4 + bt * 2 + 1][1] = r3;
            }
            #pragma unroll
            for (int mt = 0; mt < 2; mt++)
                #pragma unroll
                for (int nt = 0; nt < 8; nt++)
                    mma16816(&acc[(mt * 8 + nt) * 4], a[mt], b[nt]);
        }
    }

    // epilogue: nt 0..3 gate, nt+4 up; SwiGLU -> g_H fp16
    const int gr = lane >> 2, gc = (lane & 3) * 2;
    #pragma unroll
    for (int mt = 0; mt < 2; mt++) {
        #pragma unroll
        for (int nt = 0; nt < 4; nt++) {
            const float* g = &acc[(mt * 8 + nt) * 4];
            const float* u = &acc[(mt * 8 + nt + 4) * 4];
            int n = nB + wn + nt * 8 + gc;
            int token = mBase + wm + mt * 16 + gr;
            float h0 = g[0] * u[0] / (1.f + __expf(-g[0]));
            float h1 = g[1] * u[1] / (1.f + __expf(-g[1]));
            float h2 = g[2] * u[2] / (1.f + __expf(-g[2]));
            float h3 = g[3] * u[3] / (1.f + __expf(-g[3]));
            *(__half2*)&g_H[(size_t)token * INTER + n] = __floats2half2_rn(h0, h1);
            *(__half2*)&g_H[(size_t)(token + 8) * INTER + n] = __floats2half2_rn(h2, h3);
        }
    }
}

// ---------------- 4. down GEMM: out = h @ Wd_e (fp32 out) ----------------
__global__ __launch_bounds__(512, 1) void gemm2_kernel(float* __restrict__ out) {
    extern __shared__ __half sm[];
    __half (*sA)[BM][PAD]   = (__half(*)[BM][PAD])sm;
    __half (*sB)[BROWS][PAD] = (__half(*)[BROWS][PAD])(sm + NSTAGE * BM * PAD);

    const int tid = threadIdx.x;
    const int mBase = blockIdx.x * BM;
    const int nB = blockIdx.y * 256;
    const int e = blockIdx.x >> 4;
    const int NK = INTER / BK;                // 44

    const int lr = tid >> 2, lc = (tid & 3) * 8;
    const __half* gA = g_H + (size_t)(mBase + lr) * INTER + lc;
    const __half* gB0 = g_Wd + ((size_t)e * HIDDEN + nB + lr) * INTER + lc;
    const __half* gB1 = gB0 + (size_t)128 * INTER;

    uint32_t aAd[NSTAGE], bAd0[NSTAGE], bAd1[NSTAGE];
    #pragma unroll
    for (int s = 0; s < NSTAGE; s++) {
        aAd[s]  = smem_u32(&sA[s][lr][lc]);
        bAd0[s] = smem_u32(&sB[s][lr][lc]);
        bAd1[s] = smem_u32(&sB[s][lr + 128][lc]);
    }
    auto load_stage = [&](int s, int k0) {
        cp_async16(aAd[s],  gA  + k0);
        cp_async16(bAd0[s], gB0 + k0);
        cp_async16(bAd1[s], gB1 + k0);
    };

    float acc[2 * 8 * 4];
    #pragma unroll
    for (int i = 0; i < 64; i++) acc[i] = 0.f;

    const int w = tid >> 5, lane = tid & 31;
    const int wm = (w >> 2) * 32;
    const int wn = (w & 3) * 64;              // 0,64,128,192 (within 256 cols)
    const int lrow = lane & 15;
    const int lkb = (lane >> 4) * 8;

    #pragma unroll
    for (int i = 0; i < NSTAGE - 1; i++) { load_stage(i, i * BK); cp_commit(); }

    #pragma unroll 1
    for (int k = 0; k < NK; ++k) {
        cp_wait<NSTAGE - 2>();
        __syncthreads();
        int kn = k + NSTAGE - 1;
        if (kn < NK) load_stage(kn & 3, kn * BK);
        cp_commit();
        const int st = k & 3;
        #pragma unroll
        for (int kk = 0; kk < BK; kk += 16) {
            uint32_t a[2][4];
            uint32_t b[8][2];
            #pragma unroll
            for (int mt = 0; mt < 2; mt++)
                ldsm_x4(smem_u32(&sA[st][wm + mt * 16 + lrow][kk + lkb]),
                        a[mt][0], a[mt][1], a[mt][2], a[mt][3]);
            #pragma unroll
            for (int bt = 0; bt < 4; bt++) {
                uint32_t r0, r1, r2, r3;
                ldsm_x4(smem_u32(&sB[st][wn + bt * 16 + lrow][kk + lkb]), r0, r1, r2, r3);
                b[bt * 2][0] = r0;     b[bt * 2][1] = r2;
                b[bt * 2 + 1][0] = r1; b[bt * 2 + 1][1] = r3;
            }
            #pragma unroll
            for (int mt = 0; mt < 2; mt++)
                #pragma unroll
                for (int nt = 0; nt < 8; nt++)
                    mma16816(&acc[(mt * 8 + nt) * 4], a[mt], b[nt]);
        }
    }

    const int gr = lane >> 2, gc = (lane & 3) * 2;
    #pragma unroll
    for (int mt = 0; mt < 2; mt++) {
        #pragma unroll
        for (int nt = 0; nt < 8; nt++) {
            const float* c = &acc[(mt * 8 + nt) * 4];
            int n = nB + wn + nt * 8 + gc;
            int token = mBase + wm + mt * 16 + gr;
            *(float2*)&out[(size_t)token * HIDDEN + n] = make_float2(c[0], c[1]);
            *(float2*)&out[(size_t)(token + 8) * HIDDEN + n] = make_float2(c[2], c[3]);
        }
    }
}

// ---------------- launch ----------------
extern "C" void kernel_launch(void* const* d_in, const int* in_sizes, int n_in,
                              void* d_out, int out_size) {
    const float* x  = (const float*)d_in[0];
    const float* wg = (const float*)d_in[1];
    const float* wu = (const float*)d_in[2];
    const float* wd = (const float*)d_in[3];
    (void)in_sizes; (void)n_in; (void)out_size;

    cudaFuncSetAttribute(gemm1_kernel, cudaFuncAttributeMaxDynamicSharedMemorySize,
                         SMEM_BYTES);
    cudaFuncSetAttribute(gemm2_kernel, cudaFuncAttributeMaxDynamicSharedMemorySize,
                         SMEM_BYTES);

    // 1. X -> fp16
    size_t n8 = (size_t)TOKENS * HIDDEN / 8;
    convert_x_kernel<<<(unsigned)((n8 + 255) / 256), 256>>>(x, n8);

    // 2. weights -> fp16 transposed [e][n][k]
    wconv_kernel<<<dim3(INTER / 64, HIDDEN / 64, NEXP), 256>>>(wg, 0, HIDDEN, INTER);
    wconv_kernel<<<dim3(INTER / 64, HIDDEN / 64, NEXP), 256>>>(wu, 1, HIDDEN, INTER);
    wconv_kernel<<<dim3(HIDDEN / 64, INTER / 64, NEXP), 256>>>(wd, 2, INTER, HIDDEN);

    // 3. fused gate+up+swiglu -> g_H
    gemm1_kernel<<<dim3(TOKENS / BM, INTER / 128), 512, SMEM_BYTES>>>();

    // 4. down GEMM -> d_out
    gemm2_kernel<<<dim3(TOKENS / BM, HIDDEN / 256), 512, SMEM_BYTES>>>((float*)d_out);
}